// round 8
// baseline (speedup 1.0000x reference)
#include <cuda_runtime.h>
#include <math.h>

#define NN 4096
#define NB 8
#define NH 3
#define NF 128
#define AL 0.2f

// Scratch (device globals — no allocation allowed)
__device__ float4 g_V4[NN];          // (Wh0, Wh1, Wh2, dst_j)
__device__ float4 g_B4[NN / 2];      // pairs: (B_j, B'_j, B_{j+1}, B'_{j+1})
__device__ float  g_src[NN];
__device__ float4 g_A4[NN];          // (A_i, A'_i, src_i, 0)
__device__ float  g_meanWh[3];
__device__ float  g_h[NB * NN * NH]; // elu(h), layout [B][N*H]

// ---------------------------------------------------------------------------
// Kernel 1a: Wh = emb @ W ; src/dst projections ; per-j exponentials.
// One warp per row; lane handles 4 features. 512 CTAs x 256 threads.
// ---------------------------------------------------------------------------
__global__ void __launch_bounds__(256) k_prep(const float* __restrict__ emb,
                                              const float* __restrict__ W,
                                              const float* __restrict__ av) {
  __shared__ float sW[NF * 3];
  const int t = threadIdx.x;
  for (int x = t; x < NF * 3; x += 256) sW[x] = W[x];
  __syncthreads();

  const int warp = t >> 5, lane = t & 31;
  const int i = blockIdx.x * 8 + warp;
  const float4 e = ((const float4*)(emb + (size_t)i * NF))[lane];
  const int k0 = lane * 4;
  float h0, h1, h2;
  h0 = e.x * sW[(k0 + 0) * 3 + 0] + e.y * sW[(k0 + 1) * 3 + 0]
     + e.z * sW[(k0 + 2) * 3 + 0] + e.w * sW[(k0 + 3) * 3 + 0];
  h1 = e.x * sW[(k0 + 0) * 3 + 1] + e.y * sW[(k0 + 1) * 3 + 1]
     + e.z * sW[(k0 + 2) * 3 + 1] + e.w * sW[(k0 + 3) * 3 + 1];
  h2 = e.x * sW[(k0 + 0) * 3 + 2] + e.y * sW[(k0 + 1) * 3 + 2]
     + e.z * sW[(k0 + 2) * 3 + 2] + e.w * sW[(k0 + 3) * 3 + 2];
#pragma unroll
  for (int o = 16; o > 0; o >>= 1) {
    h0 += __shfl_xor_sync(0xffffffffu, h0, o);
    h1 += __shfl_xor_sync(0xffffffffu, h1, o);
    h2 += __shfl_xor_sync(0xffffffffu, h2, o);
  }
  if (lane == 0) {
    const float s = h0 * __ldg(av + 0) + h1 * __ldg(av + 1) + h2 * __ldg(av + 2);
    const float d = h0 * __ldg(av + 3) + h1 * __ldg(av + 4) + h2 * __ldg(av + 5);
    g_V4[i] = make_float4(h0, h1, h2, d);
    ((float2*)g_B4)[i] = make_float2(__expf(d), __expf(AL * d));
    g_src[i] = s;
  }
}

// ---------------------------------------------------------------------------
// Kernel 1b (single CTA): dst_max, meanWh, per-i exponentials
// ---------------------------------------------------------------------------
__global__ void k_prep2() {
  int t = threadIdx.x;
  float dmax = -3.4e38f, s0 = 0.f, s1 = 0.f, s2 = 0.f;
#pragma unroll
  for (int q = 0; q < 4; q++) {
    float4 v = g_V4[t + q * 1024];
    dmax = fmaxf(dmax, v.w);
    s0 += v.x; s1 += v.y; s2 += v.z;
  }
#pragma unroll
  for (int o = 16; o > 0; o >>= 1) {
    dmax = fmaxf(dmax, __shfl_xor_sync(0xffffffffu, dmax, o));
    s0 += __shfl_xor_sync(0xffffffffu, s0, o);
    s1 += __shfl_xor_sync(0xffffffffu, s1, o);
    s2 += __shfl_xor_sync(0xffffffffu, s2, o);
  }
  __shared__ float sm[32], a0[32], a1[32], a2[32], bc[1];
  int w = t >> 5, l = t & 31;
  if (l == 0) { sm[w] = dmax; a0[w] = s0; a1[w] = s1; a2[w] = s2; }
  __syncthreads();
  if (w == 0) {
    dmax = sm[l]; s0 = a0[l]; s1 = a1[l]; s2 = a2[l];
#pragma unroll
    for (int o = 16; o > 0; o >>= 1) {
      dmax = fmaxf(dmax, __shfl_xor_sync(0xffffffffu, dmax, o));
      s0 += __shfl_xor_sync(0xffffffffu, s0, o);
      s1 += __shfl_xor_sync(0xffffffffu, s1, o);
      s2 += __shfl_xor_sync(0xffffffffu, s2, o);
    }
    if (l == 0) {
      bc[0] = dmax;
      g_meanWh[0] = s0 / (float)NN;
      g_meanWh[1] = s1 / (float)NN;
      g_meanWh[2] = s2 / (float)NN;
    }
  }
  __syncthreads();
  float dstmax = bc[0];
#pragma unroll
  for (int q = 0; q < 4; q++) {
    int i = t + q * 1024;
    float s = g_src[i];
    float M = s + dstmax;
    M = M > 0.f ? M : AL * M;           // leaky-relu of unmasked row max
    g_A4[i] = make_float4(__expf(s - M), __expf(AL * s - M), s, 0.f);
  }
}

// ---------------------------------------------------------------------------
// Kernel 2: fused masked-softmax + attn@Wh over adj stream
// One row per CTA x 8 batches x all 4096 j. 256 threads, 4096 CTAs.
// ---------------------------------------------------------------------------
__device__ __forceinline__ float wsel(float tt, float Ai, float Ai2, float Bp, float Bn) {
  return (tt > 0.f ? Ai : Ai2) * (tt > 0.f ? Bp : Bn);
}
__device__ __forceinline__ float wmask(float w, int av) {
  return __int_as_float(__float_as_int(w) & (-av));  // adj in {0,1}
}

__global__ void __launch_bounds__(256) k_main(const int* __restrict__ adj) {
  const int t = threadIdx.x;
  const int i = blockIdx.x;
  __shared__ float4 sred[8];
  if (t < 8) sred[t] = make_float4(0.f, 0.f, 0.f, 0.f);
  __syncthreads();

  const float4 A0 = g_A4[i];
  const float Ai = A0.x, Ai2 = A0.y, s = A0.z;

  float4 acc[8];
#pragma unroll
  for (int b = 0; b < 8; b++) acc[b] = make_float4(0.f, 0.f, 0.f, 0.f);

  const int4* adj4 = (const int4*)adj;
  const unsigned base = (unsigned)i * (NN / 4) + (unsigned)t;

#pragma unroll
  for (int k = 0; k < 4; k++) {
    const int j = 4 * (t + 256 * k);
    const float4 v0 = __ldg(&g_V4[j + 0]);
    const float4 v1 = __ldg(&g_V4[j + 1]);
    const float4 v2 = __ldg(&g_V4[j + 2]);
    const float4 v3 = __ldg(&g_V4[j + 3]);
    const float4 bA = __ldg(&g_B4[(j >> 1) + 0]);
    const float4 bB = __ldg(&g_B4[(j >> 1) + 1]);
    const float w0 = wsel(s + v0.w, Ai, Ai2, bA.x, bA.y);
    const float w1 = wsel(s + v1.w, Ai, Ai2, bA.z, bA.w);
    const float w2 = wsel(s + v2.w, Ai, Ai2, bB.x, bB.y);
    const float w3 = wsel(s + v3.w, Ai, Ai2, bB.z, bB.w);
#pragma unroll
    for (int b = 0; b < 8; b++) {
      const int4 avv = __ldg(&adj4[base + (unsigned)b * (NN * (NN / 4))
                                        + (unsigned)k * 256u]);
      float4 A = acc[b];
      float m;
      m = wmask(w0, avv.x); A.x = fmaf(m, v0.x, A.x); A.y = fmaf(m, v0.y, A.y); A.z = fmaf(m, v0.z, A.z); A.w += m;
      m = wmask(w1, avv.y); A.x = fmaf(m, v1.x, A.x); A.y = fmaf(m, v1.y, A.y); A.z = fmaf(m, v1.z, A.z); A.w += m;
      m = wmask(w2, avv.z); A.x = fmaf(m, v2.x, A.x); A.y = fmaf(m, v2.y, A.y); A.z = fmaf(m, v2.z, A.z); A.w += m;
      m = wmask(w3, avv.w); A.x = fmaf(m, v3.x, A.x); A.y = fmaf(m, v3.y, A.y); A.z = fmaf(m, v3.z, A.z); A.w += m;
      acc[b] = A;
    }
  }

  // Cross-thread reduction: warp butterfly, then SMEM atomics (8 warps)
#pragma unroll
  for (int b = 0; b < 8; b++) {
    float4 v = acc[b];
#pragma unroll
    for (int o = 16; o > 0; o >>= 1) {
      v.x += __shfl_xor_sync(0xffffffffu, v.x, o);
      v.y += __shfl_xor_sync(0xffffffffu, v.y, o);
      v.z += __shfl_xor_sync(0xffffffffu, v.z, o);
      v.w += __shfl_xor_sync(0xffffffffu, v.w, o);
    }
    if ((t & 31) == 0) {
      atomicAdd(&sred[b].x, v.x);
      atomicAdd(&sred[b].y, v.y);
      atomicAdd(&sred[b].z, v.z);
      atomicAdd(&sred[b].w, v.w);
    }
  }
  __syncthreads();

  if (t < 8) {
    const int b = t;
    const float4 r = sred[b];
    float h0, h1, h2;
    if (r.w > 0.f) {
      const float inv = 1.0f / r.w;
      h0 = r.x * inv; h1 = r.y * inv; h2 = r.z * inv;
    } else {                      // fully-masked row -> uniform attention
      h0 = g_meanWh[0]; h1 = g_meanWh[1]; h2 = g_meanWh[2];
    }
    h0 = h0 > 0.f ? h0 : expm1f(h0);
    h1 = h1 > 0.f ? h1 : expm1f(h1);
    h2 = h2 > 0.f ? h2 : expm1f(h2);
    float* o = g_h + ((size_t)b * NN + i) * NH;
    o[0] = h0; o[1] = h1; o[2] = h2;
  }
}

// ---------------------------------------------------------------------------
// Kernel 3a: out[b][o] = fc1_b[o]  (bias pre-init; k_fc accumulates on top)
// ---------------------------------------------------------------------------
__global__ void k_init(const float* __restrict__ fb, float* __restrict__ out) {
  const int x = threadIdx.x;            // 800 threads: b*100+o
  if (x < 800) out[x] = __ldg(fb + (x % 100));
}

// ---------------------------------------------------------------------------
// Kernel 3b: out[b][o] += elu(h)_flat[b] . fc1_w[o], split over 8 m-chunks
// ---------------------------------------------------------------------------
__global__ void __launch_bounds__(256) k_fc(const float* __restrict__ fw,
                                            float* __restrict__ out) {
  const int o = blockIdx.x;             // 0..99
  const int c = blockIdx.y;             // 0..7
  const int t = threadIdx.x;
  const int M = NN * NH;                // 12288
  const int CH = M / 8;                 // 1536
  const int m0 = c * CH;
  const float* wr = fw + (size_t)o * M;

  float acc[8];
#pragma unroll
  for (int b = 0; b < 8; b++) acc[b] = 0.f;
#pragma unroll
  for (int q = 0; q < CH / 256; q++) {
    const int m = m0 + q * 256 + t;
    const float wv = __ldg(wr + m);
#pragma unroll
    for (int b = 0; b < 8; b++) acc[b] = fmaf(wv, g_h[b * M + m], acc[b]);
  }
#pragma unroll
  for (int b = 0; b < 8; b++) {
    float v = acc[b];
#pragma unroll
    for (int oo = 16; oo > 0; oo >>= 1) v += __shfl_xor_sync(0xffffffffu, v, oo);
    if ((t & 31) == 0) atomicAdd(&out[b * 100 + o], v);
  }
}

// ---------------------------------------------------------------------------
extern "C" void kernel_launch(void* const* d_in, const int* in_sizes, int n_in,
                              void* d_out, int out_size) {
  const int*   adj = (const int*)d_in[0];
  const float* emb = (const float*)d_in[1];
  const float* W   = (const float*)d_in[2];
  const float* a   = (const float*)d_in[3];
  const float* fw  = (const float*)d_in[4];
  const float* fb  = (const float*)d_in[5];
  float* out = (float*)d_out;

  k_init<<<1, 800>>>(fb, out);
  k_prep<<<NN / 8, 256>>>(emb, W, a);
  k_prep2<<<1, 1024>>>();
  k_main<<<NN, 256>>>(adj);
  dim3 g(100, 8);
  k_fc<<<g, 256>>>(fw, out);
}

// round 9
// speedup vs baseline: 1.5215x; 1.5215x over previous
#include <cuda_runtime.h>
#include <math.h>

#define NN 4096
#define NB 8
#define NH 3
#define NF 128
#define AL 0.2f

// Scratch (device globals — no allocation allowed)
__device__ float4 g_V4[NN];          // (Wh0, Wh1, Wh2, dst_j)
__device__ float4 g_B4[NN / 2];      // pairs: (B_j, B'_j, B_{j+1}, B'_{j+1})
__device__ float  g_dst[NN];         // dst_j (separate for cheap prologue loads)
__device__ float  g_src[NN];
__device__ float4 g_A4[NN];          // (A_i, A'_i, src_i, 0)
__device__ float  g_meanWh[3];
__device__ float  g_h[NB * NN * NH]; // elu(h), layout [B][N*H]

// ---------------------------------------------------------------------------
// Kernel 1a: Wh = emb @ W ; src/dst projections ; per-j exponentials.
// One warp per row; lane handles 4 features. 512 CTAs x 256 threads.
// ---------------------------------------------------------------------------
__global__ void __launch_bounds__(256) k_prep(const float* __restrict__ emb,
                                              const float* __restrict__ W,
                                              const float* __restrict__ av) {
  __shared__ float sW[NF * 3];
  const int t = threadIdx.x;
  for (int x = t; x < NF * 3; x += 256) sW[x] = W[x];
  __syncthreads();

  const int warp = t >> 5, lane = t & 31;
  const int i = blockIdx.x * 8 + warp;
  const float4 e = ((const float4*)(emb + (size_t)i * NF))[lane];
  const int k0 = lane * 4;
  float h0, h1, h2;
  h0 = e.x * sW[(k0 + 0) * 3 + 0] + e.y * sW[(k0 + 1) * 3 + 0]
     + e.z * sW[(k0 + 2) * 3 + 0] + e.w * sW[(k0 + 3) * 3 + 0];
  h1 = e.x * sW[(k0 + 0) * 3 + 1] + e.y * sW[(k0 + 1) * 3 + 1]
     + e.z * sW[(k0 + 2) * 3 + 1] + e.w * sW[(k0 + 3) * 3 + 1];
  h2 = e.x * sW[(k0 + 0) * 3 + 2] + e.y * sW[(k0 + 1) * 3 + 2]
     + e.z * sW[(k0 + 2) * 3 + 2] + e.w * sW[(k0 + 3) * 3 + 2];
#pragma unroll
  for (int o = 16; o > 0; o >>= 1) {
    h0 += __shfl_xor_sync(0xffffffffu, h0, o);
    h1 += __shfl_xor_sync(0xffffffffu, h1, o);
    h2 += __shfl_xor_sync(0xffffffffu, h2, o);
  }
  if (lane == 0) {
    const float s = h0 * __ldg(av + 0) + h1 * __ldg(av + 1) + h2 * __ldg(av + 2);
    const float d = h0 * __ldg(av + 3) + h1 * __ldg(av + 4) + h2 * __ldg(av + 5);
    g_V4[i] = make_float4(h0, h1, h2, d);
    ((float2*)g_B4)[i] = make_float2(__expf(d), __expf(AL * d));
    g_dst[i] = d;
    g_src[i] = s;
  }
}

// ---------------------------------------------------------------------------
// Kernel 1b (single CTA): dst_max, meanWh, per-i exponentials
// ---------------------------------------------------------------------------
__global__ void k_prep2() {
  int t = threadIdx.x;
  float dmax = -3.4e38f, s0 = 0.f, s1 = 0.f, s2 = 0.f;
#pragma unroll
  for (int q = 0; q < 4; q++) {
    float4 v = g_V4[t + q * 1024];
    dmax = fmaxf(dmax, v.w);
    s0 += v.x; s1 += v.y; s2 += v.z;
  }
#pragma unroll
  for (int o = 16; o > 0; o >>= 1) {
    dmax = fmaxf(dmax, __shfl_xor_sync(0xffffffffu, dmax, o));
    s0 += __shfl_xor_sync(0xffffffffu, s0, o);
    s1 += __shfl_xor_sync(0xffffffffu, s1, o);
    s2 += __shfl_xor_sync(0xffffffffu, s2, o);
  }
  __shared__ float sm[32], a0[32], a1[32], a2[32], bc[1];
  int w = t >> 5, l = t & 31;
  if (l == 0) { sm[w] = dmax; a0[w] = s0; a1[w] = s1; a2[w] = s2; }
  __syncthreads();
  if (w == 0) {
    dmax = sm[l]; s0 = a0[l]; s1 = a1[l]; s2 = a2[l];
#pragma unroll
    for (int o = 16; o > 0; o >>= 1) {
      dmax = fmaxf(dmax, __shfl_xor_sync(0xffffffffu, dmax, o));
      s0 += __shfl_xor_sync(0xffffffffu, s0, o);
      s1 += __shfl_xor_sync(0xffffffffu, s1, o);
      s2 += __shfl_xor_sync(0xffffffffu, s2, o);
    }
    if (l == 0) {
      bc[0] = dmax;
      g_meanWh[0] = s0 / (float)NN;
      g_meanWh[1] = s1 / (float)NN;
      g_meanWh[2] = s2 / (float)NN;
    }
  }
  __syncthreads();
  float dstmax = bc[0];
#pragma unroll
  for (int q = 0; q < 4; q++) {
    int i = t + q * 1024;
    float s = g_src[i];
    float M = s + dstmax;
    M = M > 0.f ? M : AL * M;           // leaky-relu of unmasked row max
    g_A4[i] = make_float4(__expf(s - M), __expf(AL * s - M), s, 0.f);
  }
}

// ---------------------------------------------------------------------------
// Kernel 2: fused masked-softmax + attn@Wh over adj stream.
// One row per CTA x 8 batches. Per-row weights w_j precomputed in SMEM.
// __launch_bounds__(256,3): cap regs at 85 -> 3 CTAs/SM -> 24 warps.
// ---------------------------------------------------------------------------
__device__ __forceinline__ float wsel(float tt, float Ai, float Ai2, float Bp, float Bn) {
  return (tt > 0.f ? Ai : Ai2) * (tt > 0.f ? Bp : Bn);
}
__device__ __forceinline__ float wmask(float w, int av) {
  return __int_as_float(__float_as_int(w) & (-av));  // adj in {0,1}
}

__global__ void __launch_bounds__(256, 3) k_main(const int* __restrict__ adj) {
  __shared__ float sw[NN];       // 16 KB: masked-softmax numerators for this row
  __shared__ float4 sred[8];
  const int t = threadIdx.x;
  const int i = blockIdx.x;
  if (t < 8) sred[t] = make_float4(0.f, 0.f, 0.f, 0.f);

  // Prologue: w_j = exp-factored leakyrelu softmax numerator, once per CTA.
  {
    const float4 A0 = g_A4[i];
    const float Ai = A0.x, Ai2 = A0.y, s = A0.z;
#pragma unroll
    for (int q = 0; q < 4; q++) {
      const int j4 = t + 256 * q;                       // float4 group index
      const float4 d4 = __ldg(&((const float4*)g_dst)[j4]);
      const float4 bA = __ldg(&g_B4[2 * j4 + 0]);
      const float4 bB = __ldg(&g_B4[2 * j4 + 1]);
      float4 w;
      w.x = wsel(s + d4.x, Ai, Ai2, bA.x, bA.y);
      w.y = wsel(s + d4.y, Ai, Ai2, bA.z, bA.w);
      w.z = wsel(s + d4.z, Ai, Ai2, bB.x, bB.y);
      w.w = wsel(s + d4.w, Ai, Ai2, bB.z, bB.w);
      ((float4*)sw)[j4] = w;
    }
  }
  __syncthreads();

  float4 acc[8];
#pragma unroll
  for (int b = 0; b < 8; b++) acc[b] = make_float4(0.f, 0.f, 0.f, 0.f);

  const int4* adj4 = (const int4*)adj;
  const unsigned base = (unsigned)i * (NN / 4) + (unsigned)t;

#pragma unroll
  for (int k = 0; k < 4; k++) {
    const int j4 = t + 256 * k;
    const float4 w4 = ((const float4*)sw)[j4];
    const int j = 4 * j4;
    const float4 v0 = __ldg(&g_V4[j + 0]);
    const float4 v1 = __ldg(&g_V4[j + 1]);
    const float4 v2 = __ldg(&g_V4[j + 2]);
    const float4 v3 = __ldg(&g_V4[j + 3]);
#pragma unroll
    for (int b = 0; b < 8; b++) {
      const int4 avv = __ldcs(&adj4[base + (unsigned)b * (NN * (NN / 4))
                                         + (unsigned)k * 256u]);
      float4 A = acc[b];
      float m;
      m = wmask(w4.x, avv.x); A.x = fmaf(m, v0.x, A.x); A.y = fmaf(m, v0.y, A.y); A.z = fmaf(m, v0.z, A.z); A.w += m;
      m = wmask(w4.y, avv.y); A.x = fmaf(m, v1.x, A.x); A.y = fmaf(m, v1.y, A.y); A.z = fmaf(m, v1.z, A.z); A.w += m;
      m = wmask(w4.z, avv.z); A.x = fmaf(m, v2.x, A.x); A.y = fmaf(m, v2.y, A.y); A.z = fmaf(m, v2.z, A.z); A.w += m;
      m = wmask(w4.w, avv.w); A.x = fmaf(m, v3.x, A.x); A.y = fmaf(m, v3.y, A.y); A.z = fmaf(m, v3.z, A.z); A.w += m;
      acc[b] = A;
    }
  }

  // Cross-thread reduction: warp butterfly, then SMEM atomics (8 warps)
#pragma unroll
  for (int b = 0; b < 8; b++) {
    float4 v = acc[b];
#pragma unroll
    for (int o = 16; o > 0; o >>= 1) {
      v.x += __shfl_xor_sync(0xffffffffu, v.x, o);
      v.y += __shfl_xor_sync(0xffffffffu, v.y, o);
      v.z += __shfl_xor_sync(0xffffffffu, v.z, o);
      v.w += __shfl_xor_sync(0xffffffffu, v.w, o);
    }
    if ((t & 31) == 0) {
      atomicAdd(&sred[b].x, v.x);
      atomicAdd(&sred[b].y, v.y);
      atomicAdd(&sred[b].z, v.z);
      atomicAdd(&sred[b].w, v.w);
    }
  }
  __syncthreads();

  if (t < 8) {
    const int b = t;
    const float4 r = sred[b];
    float h0, h1, h2;
    if (r.w > 0.f) {
      const float inv = 1.0f / r.w;
      h0 = r.x * inv; h1 = r.y * inv; h2 = r.z * inv;
    } else {                      // fully-masked row -> uniform attention
      h0 = g_meanWh[0]; h1 = g_meanWh[1]; h2 = g_meanWh[2];
    }
    h0 = h0 > 0.f ? h0 : expm1f(h0);
    h1 = h1 > 0.f ? h1 : expm1f(h1);
    h2 = h2 > 0.f ? h2 : expm1f(h2);
    float* o = g_h + ((size_t)b * NN + i) * NH;
    o[0] = h0; o[1] = h1; o[2] = h2;
  }
}

// ---------------------------------------------------------------------------
// Kernel 3a: out[b][o] = fc1_b[o]  (bias pre-init; k_fc accumulates on top)
// ---------------------------------------------------------------------------
__global__ void k_init(const float* __restrict__ fb, float* __restrict__ out) {
  const int x = threadIdx.x;            // 800 threads: b*100+o
  if (x < 800) out[x] = __ldg(fb + (x % 100));
}

// ---------------------------------------------------------------------------
// Kernel 3b: out[b][o] += elu(h)_flat[b] . fc1_w[o], split over 8 m-chunks
// ---------------------------------------------------------------------------
__global__ void __launch_bounds__(256) k_fc(const float* __restrict__ fw,
                                            float* __restrict__ out) {
  const int o = blockIdx.x;             // 0..99
  const int c = blockIdx.y;             // 0..7
  const int t = threadIdx.x;
  const int M = NN * NH;                // 12288
  const int CH = M / 8;                 // 1536
  const int m0 = c * CH;
  const float* wr = fw + (size_t)o * M;

  float acc[8];
#pragma unroll
  for (int b = 0; b < 8; b++) acc[b] = 0.f;
#pragma unroll
  for (int q = 0; q < CH / 256; q++) {
    const int m = m0 + q * 256 + t;
    const float wv = __ldg(wr + m);
#pragma unroll
    for (int b = 0; b < 8; b++) acc[b] = fmaf(wv, g_h[b * M + m], acc[b]);
  }
#pragma unroll
  for (int b = 0; b < 8; b++) {
    float v = acc[b];
#pragma unroll
    for (int oo = 16; oo > 0; oo >>= 1) v += __shfl_xor_sync(0xffffffffu, v, oo);
    if ((t & 31) == 0) atomicAdd(&out[b * 100 + o], v);
  }
}

// ---------------------------------------------------------------------------
extern "C" void kernel_launch(void* const* d_in, const int* in_sizes, int n_in,
                              void* d_out, int out_size) {
  const int*   adj = (const int*)d_in[0];
  const float* emb = (const float*)d_in[1];
  const float* W   = (const float*)d_in[2];
  const float* a   = (const float*)d_in[3];
  const float* fw  = (const float*)d_in[4];
  const float* fb  = (const float*)d_in[5];
  float* out = (float*)d_out;

  k_init<<<1, 800>>>(fb, out);
  k_prep<<<NN / 8, 256>>>(emb, W, a);
  k_prep2<<<1, 1024>>>();
  k_main<<<NN, 256>>>(adj);
  dim3 g(100, 8);
  k_fc<<<g, 256>>>(fw, out);
}